// round 1
// baseline (speedup 1.0000x reference)
#include <cuda_runtime.h>
#include <math.h>

#define NRES  16384
#define NODES 49152
#define NEDGE 786432
#define EMB   128
#define NRAD  64

// ---------------- device scratch (static, allocation-free) ----------------
__device__ float4 g_pos[NODES];              // packed positions (x,y,z,0)
__device__ float  g_accR[NODES * 3 * NRAD];  // sum of rbf per (dst, src%3)  ~37.7MB
__device__ float  g_cnt[NODES * 3];          // edge counts per (dst, src%3)
__device__ float  g_lig[NODES * EMB];        // lig features per node        ~25MB
__device__ float  g_Wp[192 * EMB];           // W'[t*64+k][c] = ligW[k][c]*bbemb[t][c]
__device__ float  g_bp[3 * EMB];             // b'[t][c] = ligb[c]*bbemb[t][c]

// ---------------- zero accumulators ----------------
__global__ void k_zero() {
    int idx = blockIdx.x * blockDim.x + threadIdx.x;
    int stride = gridDim.x * blockDim.x;
    float4 z = make_float4(0.f, 0.f, 0.f, 0.f);
    const int n1 = (NODES * 3 * NRAD) / 4;
    float4* a = reinterpret_cast<float4*>(g_accR);
    for (int i = idx; i < n1; i += stride) a[i] = z;
    const int n2 = (NODES * 3) / 4;
    float4* cvec = reinterpret_cast<float4*>(g_cnt);
    for (int i = idx; i < n2; i += stride) cvec[i] = z;
}

// ---------------- pack positions into float4[NODES] ----------------
__global__ void k_prep_pos(const float* __restrict__ pn,
                           const float* __restrict__ pca,
                           const float* __restrict__ pc) {
    int n = blockIdx.x * blockDim.x + threadIdx.x;
    if (n >= NRES) return;
    g_pos[3 * n + 0] = make_float4(pn[3 * n], pn[3 * n + 1], pn[3 * n + 2], 0.f);
    g_pos[3 * n + 1] = make_float4(pca[3 * n], pca[3 * n + 1], pca[3 * n + 2], 0.f);
    g_pos[3 * n + 2] = make_float4(pc[3 * n], pc[3 * n + 1], pc[3 * n + 2], 0.f);
}

// ---------------- precompute fused lig weights ----------------
__global__ void k_prep_w(const float* __restrict__ ligW,
                         const float* __restrict__ ligb,
                         const float* __restrict__ bbemb) {
    int idx = blockIdx.x * blockDim.x + threadIdx.x;
    if (idx < 192 * EMB) {
        int c = idx & 127;
        int kk = idx >> 7;        // 0..191
        int t = kk / NRAD;        // src atom type
        int k = kk - t * NRAD;    // radial index
        g_Wp[idx] = ligW[k * EMB + c] * bbemb[t * EMB + c];
    }
    if (idx < 3 * EMB) {
        g_bp[idx] = ligb[idx & 127] * bbemb[idx];
    }
}

// ---------------- edge phase: accumulate rbf into (dst, src%3) buckets ----------------
__global__ void __launch_bounds__(256) k_edge(const int* __restrict__ ei) {
    int e = blockIdx.x * blockDim.x + threadIdx.x;
    if (e >= NEDGE) return;
    int i = ei[e];
    int j = ei[NEDGE + e];
    float4 pi = g_pos[i];
    float4 pj = g_pos[j];
    float dx = pi.x - pj.x, dy = pi.y - pj.y, dz = pi.z - pj.z;
    float d = sqrtf(dx * dx + dy * dy + dz * dz);
    int tj = j % 3;
    float* base = &g_accR[(i * 3 + tj) * NRAD];
    atomicAdd(&g_cnt[i * 3 + tj], 1.0f);
    const float step = 5.0f / 63.0f;
#pragma unroll
    for (int k = 0; k < NRAD; k += 4) {
        float t0 = d - (k + 0) * step;
        float t1 = d - (k + 1) * step;
        float t2 = d - (k + 2) * step;
        float t3 = d - (k + 3) * step;
        float v0 = __expf(-10.0f * t0 * t0);
        float v1 = __expf(-10.0f * t1 * t1);
        float v2 = __expf(-10.0f * t2 * t2);
        float v3 = __expf(-10.0f * t3 * t3);
#if __CUDA_ARCH__ >= 900
        unsigned long long gaddr = (unsigned long long)__cvta_generic_to_global(base + k);
        asm volatile("red.global.add.v4.f32 [%0], {%1,%2,%3,%4};"
                     :: "l"(gaddr), "f"(v0), "f"(v1), "f"(v2), "f"(v3) : "memory");
#else
        atomicAdd(base + k + 0, v0);
        atomicAdd(base + k + 1, v1);
        atomicAdd(base + k + 2, v2);
        atomicAdd(base + k + 3, v3);
#endif
    }
}

// ---------------- node phase: lig = deg*x + R_cat @ W' + counts*b' ----------------
__global__ void __launch_bounds__(128) k_lig(const float* __restrict__ bbemb) {
    __shared__ float shR[32 * 192];
    __shared__ float shc[32 * 3];
    int tid = threadIdx.x;
    int i0 = blockIdx.x * 32;
    for (int idx = tid; idx < 32 * 192; idx += 128) shR[idx] = g_accR[i0 * 192 + idx];
    if (tid < 96) shc[tid] = g_cnt[i0 * 3 + tid];
    __syncthreads();

    int c = tid;
    float acc[32];
#pragma unroll
    for (int r = 0; r < 32; r++) acc[r] = 0.f;
    const float4* shR4 = reinterpret_cast<const float4*>(shR);
#pragma unroll 1
    for (int k4 = 0; k4 < 48; k4++) {
        float w0 = g_Wp[(k4 * 4 + 0) * EMB + c];
        float w1 = g_Wp[(k4 * 4 + 1) * EMB + c];
        float w2 = g_Wp[(k4 * 4 + 2) * EMB + c];
        float w3 = g_Wp[(k4 * 4 + 3) * EMB + c];
#pragma unroll
        for (int r = 0; r < 32; r++) {
            float4 rv = shR4[r * 48 + k4];
            acc[r] = fmaf(rv.x, w0, acc[r]);
            acc[r] = fmaf(rv.y, w1, acc[r]);
            acc[r] = fmaf(rv.z, w2, acc[r]);
            acc[r] = fmaf(rv.w, w3, acc[r]);
        }
    }
    float b0 = g_bp[c], b1 = g_bp[EMB + c], b2 = g_bp[2 * EMB + c];
    float x0 = bbemb[c], x1 = bbemb[EMB + c], x2 = bbemb[2 * EMB + c];
#pragma unroll
    for (int r = 0; r < 32; r++) {
        float c0 = shc[r * 3 + 0], c1 = shc[r * 3 + 1], c2 = shc[r * 3 + 2];
        float deg = c0 + c1 + c2;
        int v = i0 + r;
        int a = v % 3;
        float xs = (a == 0) ? x0 : ((a == 1) ? x1 : x2);
        g_lig[v * EMB + c] = fmaf(deg, xs, acc[r]) + c0 * b0 + c1 * b1 + c2 * b2;
    }
}

// ---------------- residue phase ----------------
// 16 residues per block (32 "edge rows"), 128 threads (thread = emb channel).
#define TRES 16
#define ROWS 32
// dynamic smem layout (floats):
//  sh_rbf [32*64], sh_g [32*128], sh_s1 [32*128], sh_m [32*256],
//  sh_p[96], sh_q[96], sh_d[32], sh_w1[96], sh_b1s[32], sh_w2[32]
#define SMEM_RES_FLOATS (32*64 + 32*128 + 32*128 + 32*256 + 96 + 96 + 32 + 96 + 32 + 32)

__global__ void __launch_bounds__(128) k_res(
    const float* __restrict__ pn, const float* __restrict__ pca, const float* __restrict__ pc,
    const int*   __restrict__ rtype, const float* __restrict__ resemb,
    const float* __restrict__ bbW, const float* __restrict__ bbB,
    const float* __restrict__ e1W, const float* __restrict__ e1B,
    const float* __restrict__ e2aW, const float* __restrict__ e2aB,
    const float* __restrict__ e2bW, const float* __restrict__ e2bB,
    const float* __restrict__ sc1W, const float* __restrict__ sc1B,
    const float* __restrict__ sc2W, const float* __restrict__ sc2B,
    float* __restrict__ out)
{
    extern __shared__ float sm[];
    float* sh_rbf = sm;                  // 32*64
    float* sh_g   = sh_rbf + 32 * 64;    // 32*128
    float* sh_s1  = sh_g + 32 * 128;     // 32*128
    float* sh_m   = sh_s1 + 32 * 128;    // 32*256
    float* sh_p   = sh_m + 32 * 256;     // 96
    float* sh_q   = sh_p + 96;           // 96
    float* sh_d   = sh_q + 96;           // 32
    float* sh_w1  = sh_d + 32;           // 96
    float* sh_b1s = sh_w1 + 96;          // 32
    float* sh_w2  = sh_b1s + 32;         // 32

    int tid = threadIdx.x;
    int n0 = blockIdx.x * TRES;

    if (tid < 96) sh_w1[tid] = sc1W[tid];
    if (tid < 32) { sh_b1s[tid] = sc1B[tid]; sh_w2[tid] = sc2W[tid]; }
    float b2s = sc2B[0];

    // ---- phase 0: per-residue geometry ----
    if (tid < TRES) {
        int n = n0 + tid;
        float nx = pn[3 * n], ny = pn[3 * n + 1], nz = pn[3 * n + 2];
        float ax = pca[3 * n], ay = pca[3 * n + 1], az = pca[3 * n + 2];
        float cx = pc[3 * n], cy = pc[3 * n + 1], cz = pc[3 * n + 2];
        float v1x = ax - nx, v1y = ay - ny, v1z = az - nz;
        float d1 = sqrtf(v1x * v1x + v1y * v1y + v1z * v1z);
        float i1 = 1.0f / fmaxf(d1, 1e-8f);
        float f1x = v1x * i1, f1y = v1y * i1, f1z = v1z * i1;
        float v2x = cx - ax, v2y = cy - ay, v2z = cz - az;
        float d2 = sqrtf(v2x * v2x + v2y * v2y + v2z * v2z);
        float i2 = 1.0f / fmaxf(d2, 1e-8f);
        float f2x = v2x * i2, f2y = v2y * i2, f2z = v2z * i2;
        float crx = f1y * f2z - f1z * f2y;
        float cry = f1z * f2x - f1x * f2z;
        float crz = f1x * f2y - f1y * f2x;
        float dc = sqrtf(crx * crx + cry * cry + crz * crz);
        float i3 = 1.0f / fmaxf(dc, 1e-8f);
        float f3x = crx * i3, f3y = cry * i3, f3z = crz * i3;

        int r0 = 2 * tid;
        sh_d[r0] = d1;
        sh_d[r0 + 1] = d2;
        // p[k] = vec . frame_k ; q[k] = sum(frame_k)
        sh_p[r0 * 3 + 0] = v1x * f1x + v1y * f1y + v1z * f1z;
        sh_p[r0 * 3 + 1] = v1x * f2x + v1y * f2y + v1z * f2z;
        sh_p[r0 * 3 + 2] = v1x * f3x + v1y * f3y + v1z * f3z;
        sh_p[(r0 + 1) * 3 + 0] = v2x * f1x + v2y * f1y + v2z * f1z;
        sh_p[(r0 + 1) * 3 + 1] = v2x * f2x + v2y * f2y + v2z * f2z;
        sh_p[(r0 + 1) * 3 + 2] = v2x * f3x + v2y * f3y + v2z * f3z;
        float q0 = f1x + f1y + f1z;
        float q1 = f2x + f2y + f2z;
        float q2 = f3x + f3y + f3z;
        sh_q[r0 * 3 + 0] = q0; sh_q[r0 * 3 + 1] = q1; sh_q[r0 * 3 + 2] = q2;
        sh_q[(r0 + 1) * 3 + 0] = q0; sh_q[(r0 + 1) * 3 + 1] = q1; sh_q[(r0 + 1) * 3 + 2] = q2;
    }
    __syncthreads();

    // ---- phase 1: rbf for all 32 rows ----
    {
        int k = tid & 63;
        int rh = tid >> 6;
        float mu = (float)k * (5.0f / 63.0f);
#pragma unroll
        for (int r = rh; r < ROWS; r += 2) {
            float t = sh_d[r] - mu;
            sh_rbf[r * 64 + k] = __expf(-10.0f * t * t);
        }
    }
    __syncthreads();

    int c = tid;
    // ---- phase 2: radial = rbf @ bbW + b; g = radial*u*v ----
    {
        float acc[ROWS];
#pragma unroll
        for (int r = 0; r < ROWS; r++) acc[r] = 0.f;
        const float4* rb4 = reinterpret_cast<const float4*>(sh_rbf);
#pragma unroll 1
        for (int k4 = 0; k4 < 16; k4++) {
            float w0 = bbW[(k4 * 4 + 0) * EMB + c];
            float w1 = bbW[(k4 * 4 + 1) * EMB + c];
            float w2 = bbW[(k4 * 4 + 2) * EMB + c];
            float w3 = bbW[(k4 * 4 + 3) * EMB + c];
#pragma unroll
            for (int r = 0; r < ROWS; r++) {
                float4 rv = rb4[r * 16 + k4];
                acc[r] = fmaf(rv.x, w0, acc[r]);
                acc[r] = fmaf(rv.y, w1, acc[r]);
                acc[r] = fmaf(rv.z, w2, acc[r]);
                acc[r] = fmaf(rv.w, w3, acc[r]);
            }
        }
        float bb = bbB[c];
#pragma unroll
        for (int r = 0; r < ROWS; r++) {
            int n = n0 + (r >> 1);
            int a = r & 1;
            float u = g_lig[(3 * n + a) * EMB + c];
            float v = g_lig[(3 * n + a + 1) * EMB + c];
            sh_g[r * EMB + c] = (acc[r] + bb) * u * v;
        }
    }
    __syncthreads();

    // ---- phase 3: h = g @ e1W ; scalarization -> s1 ----
    {
        float acc[ROWS];
#pragma unroll
        for (int r = 0; r < ROWS; r++) acc[r] = 0.f;
        const float4* g4 = reinterpret_cast<const float4*>(sh_g);
#pragma unroll 1
        for (int k4 = 0; k4 < 32; k4++) {
            float w0 = e1W[(k4 * 4 + 0) * EMB + c];
            float w1 = e1W[(k4 * 4 + 1) * EMB + c];
            float w2 = e1W[(k4 * 4 + 2) * EMB + c];
            float w3 = e1W[(k4 * 4 + 3) * EMB + c];
#pragma unroll
            for (int r = 0; r < ROWS; r++) {
                float4 gv = g4[r * 32 + k4];
                acc[r] = fmaf(gv.x, w0, acc[r]);
                acc[r] = fmaf(gv.y, w1, acc[r]);
                acc[r] = fmaf(gv.z, w2, acc[r]);
                acc[r] = fmaf(gv.w, w3, acc[r]);
            }
        }
        // stash h values so the scalarization loop can stay rolled
#pragma unroll
        for (int r = 0; r < ROWS; r++) sh_s1[r * EMB + c] = acc[r];
        float b1c = e1B[c];
#pragma unroll 1
        for (int r = 0; r < ROWS; r++) {
            float h = sh_s1[r * EMB + c];
            float p0 = sh_p[r * 3 + 0], p1 = sh_p[r * 3 + 1], p2 = sh_p[r * 3 + 2];
            float q0 = sh_q[r * 3 + 0], q1 = sh_q[r * 3 + 1], q2 = sh_q[r * 3 + 2];
            float sc0 = h * p0 + b1c * q0;
            float sc1 = h * p1 + b1c * q1;
            float sc2 = h * p2 + b1c * q2;
            float z = 0.f;
#pragma unroll 1
            for (int m = 0; m < 32; m++) {
                float t = fmaf(sc0, sh_w1[m], fmaf(sc1, sh_w1[32 + m], fmaf(sc2, sh_w1[64 + m], sh_b1s[m])));
                float sg = __fdividef(t, 1.0f + __expf(-t));  // silu
                z = fmaf(sg, sh_w2[m], z);
            }
            sh_s1[r * EMB + c] = z + b2s + sc0;
        }
    }
    __syncthreads();

    // ---- phase 4: m = relu(s1 @ e2aW + b) [32 x 256] ----
    {
        float a0[ROWS], a1[ROWS];
#pragma unroll
        for (int r = 0; r < ROWS; r++) { a0[r] = 0.f; a1[r] = 0.f; }
        const float4* s4 = reinterpret_cast<const float4*>(sh_s1);
#pragma unroll 1
        for (int k4 = 0; k4 < 32; k4++) {
            const float* wp0 = e2aW + (k4 * 4 + 0) * 256;
            const float* wp1 = e2aW + (k4 * 4 + 1) * 256;
            const float* wp2 = e2aW + (k4 * 4 + 2) * 256;
            const float* wp3 = e2aW + (k4 * 4 + 3) * 256;
            float u00 = wp0[c], u01 = wp0[c + 128];
            float u10 = wp1[c], u11 = wp1[c + 128];
            float u20 = wp2[c], u21 = wp2[c + 128];
            float u30 = wp3[c], u31 = wp3[c + 128];
#pragma unroll
            for (int r = 0; r < ROWS; r++) {
                float4 sv = s4[r * 32 + k4];
                a0[r] = fmaf(sv.x, u00, a0[r]); a1[r] = fmaf(sv.x, u01, a1[r]);
                a0[r] = fmaf(sv.y, u10, a0[r]); a1[r] = fmaf(sv.y, u11, a1[r]);
                a0[r] = fmaf(sv.z, u20, a0[r]); a1[r] = fmaf(sv.z, u21, a1[r]);
                a0[r] = fmaf(sv.w, u30, a0[r]); a1[r] = fmaf(sv.w, u31, a1[r]);
            }
        }
        float ba0 = e2aB[c], ba1 = e2aB[c + 128];
#pragma unroll
        for (int r = 0; r < ROWS; r++) {
            sh_m[r * 256 + c] = fmaxf(a0[r] + ba0, 0.f);
            sh_m[r * 256 + 128 + c] = fmaxf(a1[r] + ba1, 0.f);
        }
    }
    __syncthreads();

    // ---- phase 5: out2 = m @ e2bW + b ; combine rows + residue emb ----
    {
        float acc[ROWS];
#pragma unroll
        for (int r = 0; r < ROWS; r++) acc[r] = 0.f;
        const float4* m4 = reinterpret_cast<const float4*>(sh_m);
#pragma unroll 1
        for (int k4 = 0; k4 < 64; k4++) {
            float w0 = e2bW[(k4 * 4 + 0) * EMB + c];
            float w1 = e2bW[(k4 * 4 + 1) * EMB + c];
            float w2 = e2bW[(k4 * 4 + 2) * EMB + c];
            float w3 = e2bW[(k4 * 4 + 3) * EMB + c];
#pragma unroll
            for (int r = 0; r < ROWS; r++) {
                float4 mv = m4[r * 64 + k4];
                acc[r] = fmaf(mv.x, w0, acc[r]);
                acc[r] = fmaf(mv.y, w1, acc[r]);
                acc[r] = fmaf(mv.z, w2, acc[r]);
                acc[r] = fmaf(mv.w, w3, acc[r]);
            }
        }
        float bb2 = e2bB[c];
#pragma unroll
        for (int i = 0; i < TRES; i++) {
            int n = n0 + i;
            float val = 0.5f * (acc[2 * i] + acc[2 * i + 1]) + bb2 + resemb[rtype[n] * EMB + c];
            out[n * EMB + c] = val;
        }
    }
}

// ---------------- launch ----------------
extern "C" void kernel_launch(void* const* d_in, const int* in_sizes, int n_in,
                              void* d_out, int out_size) {
    const float* pn    = (const float*)d_in[0];
    const float* pca   = (const float*)d_in[1];
    const float* pc    = (const float*)d_in[2];
    const int*   rtype = (const int*)  d_in[3];
    /* batch d_in[4] unused */
    const int*   eidx  = (const int*)  d_in[5];
    const float* resemb= (const float*)d_in[6];
    const float* bbemb = (const float*)d_in[7];
    const float* ligW  = (const float*)d_in[8];
    const float* ligb  = (const float*)d_in[9];
    const float* bbW   = (const float*)d_in[10];
    const float* bbB   = (const float*)d_in[11];
    const float* e1W   = (const float*)d_in[12];
    const float* e1B   = (const float*)d_in[13];
    const float* e2aW  = (const float*)d_in[14];
    const float* e2aB  = (const float*)d_in[15];
    const float* e2bW  = (const float*)d_in[16];
    const float* e2bB  = (const float*)d_in[17];
    const float* sc1W  = (const float*)d_in[18];
    const float* sc1B  = (const float*)d_in[19];
    const float* sc2W  = (const float*)d_in[20];
    const float* sc2B  = (const float*)d_in[21];
    float* out = (float*)d_out;

    size_t smem_res = SMEM_RES_FLOATS * sizeof(float);
    cudaFuncSetAttribute(k_res, cudaFuncAttributeMaxDynamicSharedMemorySize, (int)smem_res);

    k_zero<<<512, 256>>>();
    k_prep_pos<<<(NRES + 127) / 128, 128>>>(pn, pca, pc);
    k_prep_w<<<(192 * EMB + 255) / 256, 256>>>(ligW, ligb, bbemb);
    k_edge<<<NEDGE / 256, 256>>>(eidx);
    k_lig<<<NODES / 32, 128>>>(bbemb);
    k_res<<<NRES / TRES, 128, smem_res>>>(pn, pca, pc, rtype, resemb,
                                          bbW, bbB, e1W, e1B,
                                          e2aW, e2aB, e2bW, e2bB,
                                          sc1W, sc1B, sc2W, sc2B, out);
}

// round 2
// speedup vs baseline: 1.3141x; 1.3141x over previous
#include <cuda_runtime.h>
#include <math.h>

#define NRES  16384
#define NODES 49152
#define NEDGE 786432
#define EMB   128
#define NRAD  64
#define TRES  16
#define STRF  36   // activation column stride in floats (pad for bank spread, 16B-align)
#define STRD  18   // same in u64
#define STRV  9    // same in ulonglong2

typedef unsigned long long u64;

__device__ __forceinline__ u64 pk2(float lo, float hi) {
    u64 r; asm("mov.b64 %0,{%1,%2};" : "=l"(r) : "f"(lo), "f"(hi)); return r;
}
__device__ __forceinline__ void up2(u64 a, float& lo, float& hi) {
    asm("mov.b64 {%0,%1},%2;" : "=f"(lo), "=f"(hi) : "l"(a));
}
// packed fp32x2 fma: d = a*b + c  (2 FMA per inst)
__device__ __forceinline__ u64 ff2(u64 a, u64 b, u64 c) {
    u64 d; asm("fma.rn.f32x2 %0,%1,%2,%3;" : "=l"(d) : "l"(a), "l"(b), "l"(c)); return d;
}

// ---------------- device scratch ----------------
__device__ float4 g_pos[NODES];
__device__ float  g_accR[NODES * 3 * NRAD];
__device__ float  g_cnt[NODES * 3];
__device__ float  g_lig[NODES * EMB];
__device__ float  g_bp[3 * EMB];
// duplicated {w,w} packed weights
__device__ u64    g_Wp2[192 * 128];
__device__ u64    g_bbW2[64 * 128];
__device__ u64    g_e1W2[128 * 128];
__device__ u64    g_e2aW2[128 * 256];
__device__ u64    g_e2bW2[256 * 128];

// ---------------- zero accumulators ----------------
__global__ void k_zero() {
    int idx = blockIdx.x * blockDim.x + threadIdx.x;
    int stride = gridDim.x * blockDim.x;
    float4 z = make_float4(0.f, 0.f, 0.f, 0.f);
    const int n1 = (NODES * 3 * NRAD) / 4;
    float4* a = reinterpret_cast<float4*>(g_accR);
    for (int i = idx; i < n1; i += stride) a[i] = z;
    const int n2 = (NODES * 3) / 4;
    float4* cvec = reinterpret_cast<float4*>(g_cnt);
    for (int i = idx; i < n2; i += stride) cvec[i] = z;
}

__global__ void k_prep_pos(const float* __restrict__ pn,
                           const float* __restrict__ pca,
                           const float* __restrict__ pc) {
    int n = blockIdx.x * blockDim.x + threadIdx.x;
    if (n >= NRES) return;
    g_pos[3 * n + 0] = make_float4(pn[3 * n], pn[3 * n + 1], pn[3 * n + 2], 0.f);
    g_pos[3 * n + 1] = make_float4(pca[3 * n], pca[3 * n + 1], pca[3 * n + 2], 0.f);
    g_pos[3 * n + 2] = make_float4(pc[3 * n], pc[3 * n + 1], pc[3 * n + 2], 0.f);
}

__global__ void k_prep_w(const float* __restrict__ ligW,
                         const float* __restrict__ ligb,
                         const float* __restrict__ bbemb) {
    int idx = blockIdx.x * blockDim.x + threadIdx.x;
    if (idx < 192 * EMB) {
        int c = idx & 127;
        int kk = idx >> 7;
        int t = kk / NRAD;
        int k = kk - t * NRAD;
        float v = ligW[k * EMB + c] * bbemb[t * EMB + c];
        g_Wp2[idx] = pk2(v, v);
    }
    if (idx < 3 * EMB) g_bp[idx] = ligb[idx & 127] * bbemb[idx];
}

__global__ void k_prep_wd(const float* __restrict__ bbW, const float* __restrict__ e1W,
                          const float* __restrict__ e2aW, const float* __restrict__ e2bW) {
    int i = blockIdx.x * blockDim.x + threadIdx.x;
    if (i < 64 * 128)  g_bbW2[i]  = pk2(bbW[i],  bbW[i]);
    if (i < 128 * 128) g_e1W2[i]  = pk2(e1W[i],  e1W[i]);
    if (i < 128 * 256) g_e2aW2[i] = pk2(e2aW[i], e2aW[i]);
    if (i < 256 * 128) g_e2bW2[i] = pk2(e2bW[i], e2bW[i]);
}

// ---------------- edge phase with distance cutoff ----------------
// rbf = exp(-10*(d-mu)^2), mu in [0,5]; for d^2 > 44 (d>6.63) max term < 3e-12 -> skip.
__global__ void __launch_bounds__(256) k_edge(const int* __restrict__ ei) {
    int e = blockIdx.x * blockDim.x + threadIdx.x;
    if (e >= NEDGE) return;
    int i = ei[e];
    int j = ei[NEDGE + e];
    float4 pi = g_pos[i];
    float4 pj = g_pos[j];
    float dx = pi.x - pj.x, dy = pi.y - pj.y, dz = pi.z - pj.z;
    float d2 = dx * dx + dy * dy + dz * dz;
    int tj = j % 3;
    atomicAdd(&g_cnt[i * 3 + tj], 1.0f);
    if (d2 < 44.0f) {
        float d = sqrtf(d2);
        float* base = &g_accR[(i * 3 + tj) * NRAD];
        const float step = 5.0f / 63.0f;
#pragma unroll
        for (int k = 0; k < NRAD; k += 4) {
            float t0 = d - (k + 0) * step;
            float t1 = d - (k + 1) * step;
            float t2 = d - (k + 2) * step;
            float t3 = d - (k + 3) * step;
            float v0 = __expf(-10.0f * t0 * t0);
            float v1 = __expf(-10.0f * t1 * t1);
            float v2 = __expf(-10.0f * t2 * t2);
            float v3 = __expf(-10.0f * t3 * t3);
            unsigned long long gaddr = (unsigned long long)__cvta_generic_to_global(base + k);
            asm volatile("red.global.add.v4.f32 [%0], {%1,%2,%3,%4};"
                         :: "l"(gaddr), "f"(v0), "f"(v1), "f"(v2), "f"(v3) : "memory");
        }
    }
}

// ---------------- FMA2 GEMM helpers ----------------
// Activations X: column-major [K][32 rows] with column stride STRF floats.
// Row-pairs (2rp,2rp+1) are u64; weights are pre-duplicated {w,w}.

// 8 row-pairs (half of the 32 rows), 2 output channels.
template<int K>
__device__ __forceinline__ void gemm8(const ulonglong2* __restrict__ X, int half,
                                      const u64* __restrict__ W2, int ldw,
                                      int c0, int c1, u64* aA, u64* aB) {
#pragma unroll
    for (int i = 0; i < 8; i++) { aA[i] = 0ull; aB[i] = 0ull; }
    const ulonglong2* xp = X + 4 * half;
#pragma unroll 2
    for (int k = 0; k < K; k++) {
        u64 w0 = __ldg(&W2[k * ldw + c0]);
        u64 w1 = __ldg(&W2[k * ldw + c1]);
#pragma unroll
        for (int r2 = 0; r2 < 4; r2++) {
            ulonglong2 x = xp[k * STRV + r2];
            aA[2 * r2]     = ff2(x.x, w0, aA[2 * r2]);
            aA[2 * r2 + 1] = ff2(x.y, w0, aA[2 * r2 + 1]);
            aB[2 * r2]     = ff2(x.x, w1, aB[2 * r2]);
            aB[2 * r2 + 1] = ff2(x.y, w1, aB[2 * r2 + 1]);
        }
    }
}

// all 16 row-pairs, 2 output channels (for the 256-wide hidden layer).
template<int K>
__device__ __forceinline__ void gemm16(const ulonglong2* __restrict__ X,
                                       const u64* __restrict__ W2, int ldw,
                                       int c0, int c1, u64* aA, u64* aB) {
#pragma unroll
    for (int i = 0; i < 16; i++) { aA[i] = 0ull; aB[i] = 0ull; }
#pragma unroll 2
    for (int k = 0; k < K; k++) {
        u64 w0 = __ldg(&W2[k * ldw + c0]);
        u64 w1 = __ldg(&W2[k * ldw + c1]);
#pragma unroll
        for (int r2 = 0; r2 < 8; r2++) {
            ulonglong2 x = X[k * STRV + r2];
            aA[2 * r2]     = ff2(x.x, w0, aA[2 * r2]);
            aA[2 * r2 + 1] = ff2(x.y, w0, aA[2 * r2 + 1]);
            aB[2 * r2]     = ff2(x.x, w1, aB[2 * r2]);
            aB[2 * r2 + 1] = ff2(x.y, w1, aB[2 * r2 + 1]);
        }
    }
}

// ---------------- node phase: lig = deg*x + R_cat @ W' + counts*b' ----------------
__global__ void __launch_bounds__(128) k_lig(const float* __restrict__ bbemb) {
    __shared__ __align__(16) float shT[192 * STRF];
    __shared__ float shc[96];
    int tid = threadIdx.x;
    int i0 = blockIdx.x * 32;
    // load + transpose accR into column-major [k][row]
    const float4* gR = (const float4*)(g_accR + (size_t)i0 * 192);
    for (int q = tid; q < 1536; q += 128) {
        int r = q / 48, k4 = q - 48 * r;
        float4 v = gR[q];
        int kb = 4 * k4;
        shT[(kb + 0) * STRF + r] = v.x;
        shT[(kb + 1) * STRF + r] = v.y;
        shT[(kb + 2) * STRF + r] = v.z;
        shT[(kb + 3) * STRF + r] = v.w;
    }
    if (tid < 96) shc[tid] = g_cnt[i0 * 3 + tid];
    __syncthreads();

    int c0 = tid & 63, half = tid >> 6, c1 = c0 + 64;
    u64 aA[8], aB[8];
    gemm8<192>((const ulonglong2*)shT, half, g_Wp2, 128, c0, c1, aA, aB);

    float b00 = g_bp[c0], b01 = g_bp[128 + c0], b02 = g_bp[256 + c0];
    float b10 = g_bp[c1], b11 = g_bp[128 + c1], b12 = g_bp[256 + c1];
    float x00 = bbemb[c0], x01 = bbemb[128 + c0], x02 = bbemb[256 + c0];
    float x10 = bbemb[c1], x11 = bbemb[128 + c1], x12 = bbemb[256 + c1];
#pragma unroll
    for (int jj = 0; jj < 8; jj++) {
        int rp = 8 * half + jj;
        int r0 = 2 * rp, r1 = r0 + 1;
        int v0 = i0 + r0, v1 = i0 + r1;
        float ca0 = shc[r0 * 3 + 0], ca1 = shc[r0 * 3 + 1], ca2 = shc[r0 * 3 + 2];
        float cb0 = shc[r1 * 3 + 0], cb1 = shc[r1 * 3 + 1], cb2 = shc[r1 * 3 + 2];
        float dga = ca0 + ca1 + ca2, dgb = cb0 + cb1 + cb2;
        int a0 = v0 % 3, a1 = v1 % 3;
        float y0, y1;
        up2(aA[jj], y0, y1);
        float xs0 = (a0 == 0) ? x00 : ((a0 == 1) ? x01 : x02);
        float xs1 = (a1 == 0) ? x00 : ((a1 == 1) ? x01 : x02);
        g_lig[v0 * EMB + c0] = fmaf(dga, xs0, y0) + ca0 * b00 + ca1 * b01 + ca2 * b02;
        g_lig[v1 * EMB + c0] = fmaf(dgb, xs1, y1) + cb0 * b00 + cb1 * b01 + cb2 * b02;
        up2(aB[jj], y0, y1);
        float xt0 = (a0 == 0) ? x10 : ((a0 == 1) ? x11 : x12);
        float xt1 = (a1 == 0) ? x10 : ((a1 == 1) ? x11 : x12);
        g_lig[v0 * EMB + c1] = fmaf(dga, xt0, y0) + ca0 * b10 + ca1 * b11 + ca2 * b12;
        g_lig[v1 * EMB + c1] = fmaf(dgb, xt1, y1) + cb0 * b10 + cb1 * b11 + cb2 * b12;
    }
}

// ---------------- residue phase ----------------
// 16 residues/block -> 32 "edge rows". 128 threads.
// Activations staged column-major in dyn smem: bufA(4608f) bufB(4608f) bufC(9216f) + smalls.
#define SMEM_RES_FLOATS (18432 + 384)

__global__ void __launch_bounds__(128) k_res(
    const float* __restrict__ pn, const float* __restrict__ pca, const float* __restrict__ pc,
    const int* __restrict__ rtype, const float* __restrict__ resemb,
    const float* __restrict__ bbB, const float* __restrict__ e1B,
    const float* __restrict__ e2aB, const float* __restrict__ e2bB,
    const float* __restrict__ sc1W, const float* __restrict__ sc1B,
    const float* __restrict__ sc2W, const float* __restrict__ sc2B,
    float* __restrict__ out)
{
    extern __shared__ float sm[];
    float* bufA = sm;                      // 4608 (rbf[64][.] then s1[128][.])
    float* bufB = sm + 4608;               // 4608 (g[128][.])
    float* bufC = sm + 9216;               // 9216 (m[256][.])
    float* sh_p = sm + 18432;              // 96
    float* sh_q = sh_p + 96;               // 96
    float* sh_d = sh_q + 96;               // 32
    float* sh_w1 = sh_d + 32;              // 96
    float* sh_b1s = sh_w1 + 96;            // 32
    float* sh_w2 = sh_b1s + 32;            // 32
    const ulonglong2* bufA2 = reinterpret_cast<const ulonglong2*>(bufA);
    const ulonglong2* bufB2 = reinterpret_cast<const ulonglong2*>(bufB);
    const ulonglong2* bufC2 = reinterpret_cast<const ulonglong2*>(bufC);
    u64* bufAD = reinterpret_cast<u64*>(bufA);
    u64* bufBD = reinterpret_cast<u64*>(bufB);
    u64* bufCD = reinterpret_cast<u64*>(bufC);

    int tid = threadIdx.x;
    int n0 = blockIdx.x * TRES;
    int c0 = tid & 63, half = tid >> 6, c1 = c0 + 64;

    if (tid < 96) sh_w1[tid] = sc1W[tid];
    if (tid < 32) { sh_b1s[tid] = sc1B[tid]; sh_w2[tid] = sc2W[tid]; }
    float b2s = sc2B[0];

    // ---- phase 0: per-residue geometry ----
    if (tid < TRES) {
        int n = n0 + tid;
        float nx = pn[3 * n], ny = pn[3 * n + 1], nz = pn[3 * n + 2];
        float ax = pca[3 * n], ay = pca[3 * n + 1], az = pca[3 * n + 2];
        float cx = pc[3 * n], cy = pc[3 * n + 1], cz = pc[3 * n + 2];
        float v1x = ax - nx, v1y = ay - ny, v1z = az - nz;
        float d1 = sqrtf(v1x * v1x + v1y * v1y + v1z * v1z);
        float i1 = 1.0f / fmaxf(d1, 1e-8f);
        float f1x = v1x * i1, f1y = v1y * i1, f1z = v1z * i1;
        float v2x = cx - ax, v2y = cy - ay, v2z = cz - az;
        float d2 = sqrtf(v2x * v2x + v2y * v2y + v2z * v2z);
        float i2 = 1.0f / fmaxf(d2, 1e-8f);
        float f2x = v2x * i2, f2y = v2y * i2, f2z = v2z * i2;
        float crx = f1y * f2z - f1z * f2y;
        float cry = f1z * f2x - f1x * f2z;
        float crz = f1x * f2y - f1y * f2x;
        float dc = sqrtf(crx * crx + cry * cry + crz * crz);
        float i3 = 1.0f / fmaxf(dc, 1e-8f);
        float f3x = crx * i3, f3y = cry * i3, f3z = crz * i3;

        int r0 = 2 * tid;
        sh_d[r0] = d1;
        sh_d[r0 + 1] = d2;
        sh_p[r0 * 3 + 0] = v1x * f1x + v1y * f1y + v1z * f1z;
        sh_p[r0 * 3 + 1] = v1x * f2x + v1y * f2y + v1z * f2z;
        sh_p[r0 * 3 + 2] = v1x * f3x + v1y * f3y + v1z * f3z;
        sh_p[(r0 + 1) * 3 + 0] = v2x * f1x + v2y * f1y + v2z * f1z;
        sh_p[(r0 + 1) * 3 + 1] = v2x * f2x + v2y * f2y + v2z * f2z;
        sh_p[(r0 + 1) * 3 + 2] = v2x * f3x + v2y * f3y + v2z * f3z;
        float q0 = f1x + f1y + f1z;
        float q1 = f2x + f2y + f2z;
        float q2 = f3x + f3y + f3z;
        sh_q[r0 * 3 + 0] = q0; sh_q[r0 * 3 + 1] = q1; sh_q[r0 * 3 + 2] = q2;
        sh_q[(r0 + 1) * 3 + 0] = q0; sh_q[(r0 + 1) * 3 + 1] = q1; sh_q[(r0 + 1) * 3 + 2] = q2;
    }
    __syncthreads();

    // ---- phase 1: rbf, column-major [k][row] ----
    {
        int k = tid & 63;
        int rh = tid >> 6;
        float mu = (float)k * (5.0f / 63.0f);
#pragma unroll
        for (int r = rh; r < 32; r += 2) {
            float t = sh_d[r] - mu;
            bufA[k * STRF + r] = __expf(-10.0f * t * t);
        }
    }
    __syncthreads();

    // ---- phase 2: radial = rbf @ bbW + b ; g = radial*u*v ----
    {
        u64 hA[8], hB[8];
        gemm8<64>(bufA2, half, g_bbW2, 128, c0, c1, hA, hB);
        float bb0 = bbB[c0], bb1 = bbB[c1];
#pragma unroll
        for (int jj = 0; jj < 8; jj++) {
            int rp = 8 * half + jj;
            int n = n0 + rp;
            const float* L = g_lig + (size_t)(3 * n) * EMB;
            float u0a = L[c0], u1a = L[EMB + c0], u2a = L[2 * EMB + c0];
            float u0b = L[c1], u1b = L[EMB + c1], u2b = L[2 * EMB + c1];
            float h0, h1;
            up2(hA[jj], h0, h1);
            bufBD[c0 * STRD + rp] = pk2((h0 + bb0) * u0a * u1a, (h1 + bb0) * u1a * u2a);
            up2(hB[jj], h0, h1);
            bufBD[c1 * STRD + rp] = pk2((h0 + bb1) * u0b * u1b, (h1 + bb1) * u1b * u2b);
        }
    }
    __syncthreads();

    // ---- phase 3: h = g @ e1W ; scalarization + silu-MLP -> s1 ----
    {
        u64 hA[8], hB[8];
        gemm8<128>(bufB2, half, g_e1W2, 128, c0, c1, hA, hB);
        float b1c0 = e1B[c0], b1c1 = e1B[c1];
#pragma unroll 1
        for (int jj = 0; jj < 8; jj++) {
            int rp = 8 * half + jj;
            int r0 = 2 * rp, r1 = r0 + 1;
            float p00 = sh_p[r0 * 3 + 0], p01 = sh_p[r0 * 3 + 1], p02 = sh_p[r0 * 3 + 2];
            float p10 = sh_p[r1 * 3 + 0], p11 = sh_p[r1 * 3 + 1], p12 = sh_p[r1 * 3 + 2];
            float q0 = sh_q[r0 * 3 + 0], q1 = sh_q[r0 * 3 + 1], q2 = sh_q[r0 * 3 + 2];
            float hA0, hA1, hB0, hB1;
            up2(hA[jj], hA0, hA1);
            up2(hB[jj], hB0, hB1);
            // sc components: 4 (row,channel) combos
            float sA0x = hA0 * p00 + b1c0 * q0, sA0y = hA0 * p01 + b1c0 * q1, sA0z = hA0 * p02 + b1c0 * q2;
            float sA1x = hA1 * p10 + b1c0 * q0, sA1y = hA1 * p11 + b1c0 * q1, sA1z = hA1 * p12 + b1c0 * q2;
            float sB0x = hB0 * p00 + b1c1 * q0, sB0y = hB0 * p01 + b1c1 * q1, sB0z = hB0 * p02 + b1c1 * q2;
            float sB1x = hB1 * p10 + b1c1 * q0, sB1y = hB1 * p11 + b1c1 * q1, sB1z = hB1 * p12 + b1c1 * q2;
            float zA0 = 0.f, zA1 = 0.f, zB0 = 0.f, zB1 = 0.f;
#pragma unroll 1
            for (int m = 0; m < 32; m++) {
                float w0 = sh_w1[m], w1 = sh_w1[32 + m], w2 = sh_w1[64 + m];
                float bb = sh_b1s[m], wo = sh_w2[m];
                float t0 = fmaf(sA0x, w0, fmaf(sA0y, w1, fmaf(sA0z, w2, bb)));
                float t1 = fmaf(sA1x, w0, fmaf(sA1y, w1, fmaf(sA1z, w2, bb)));
                float t2 = fmaf(sB0x, w0, fmaf(sB0y, w1, fmaf(sB0z, w2, bb)));
                float t3 = fmaf(sB1x, w0, fmaf(sB1y, w1, fmaf(sB1z, w2, bb)));
                float g0 = __fdividef(t0, 1.0f + __expf(-t0));
                float g1 = __fdividef(t1, 1.0f + __expf(-t1));
                float g2 = __fdividef(t2, 1.0f + __expf(-t2));
                float g3 = __fdividef(t3, 1.0f + __expf(-t3));
                zA0 = fmaf(g0, wo, zA0);
                zA1 = fmaf(g1, wo, zA1);
                zB0 = fmaf(g2, wo, zB0);
                zB1 = fmaf(g3, wo, zB1);
            }
            bufAD[c0 * STRD + rp] = pk2(zA0 + b2s + sA0x, zA1 + b2s + sA1x);
            bufAD[c1 * STRD + rp] = pk2(zB0 + b2s + sB0x, zB1 + b2s + sB1x);
        }
    }
    __syncthreads();

    // ---- phase 4: m = relu(s1 @ e2aW + b) [rows x 256] ----
    {
        u64 mA[16], mB[16];
        gemm16<128>(bufA2, g_e2aW2, 256, tid, tid + 128, mA, mB);
        float ba0 = e2aB[tid], ba1 = e2aB[tid + 128];
#pragma unroll
        for (int rp = 0; rp < 16; rp++) {
            float x0, x1;
            up2(mA[rp], x0, x1);
            bufCD[tid * STRD + rp] = pk2(fmaxf(x0 + ba0, 0.f), fmaxf(x1 + ba0, 0.f));
            up2(mB[rp], x0, x1);
            bufCD[(tid + 128) * STRD + rp] = pk2(fmaxf(x0 + ba1, 0.f), fmaxf(x1 + ba1, 0.f));
        }
    }
    __syncthreads();

    // ---- phase 5: y = m @ e2bW + b ; combine rows + residue emb ----
    {
        u64 yA[8], yB[8];
        gemm8<256>(bufC2, half, g_e2bW2, 128, c0, c1, yA, yB);
        float bb2_0 = e2bB[c0], bb2_1 = e2bB[c1];
#pragma unroll
        for (int jj = 0; jj < 8; jj++) {
            int rp = 8 * half + jj;
            int n = n0 + rp;
            int rt = rtype[n];
            float y0, y1;
            up2(yA[jj], y0, y1);
            out[n * EMB + c0] = 0.5f * (y0 + y1) + bb2_0 + resemb[rt * EMB + c0];
            up2(yB[jj], y0, y1);
            out[n * EMB + c1] = 0.5f * (y0 + y1) + bb2_1 + resemb[rt * EMB + c1];
        }
    }
}

// ---------------- launch ----------------
extern "C" void kernel_launch(void* const* d_in, const int* in_sizes, int n_in,
                              void* d_out, int out_size) {
    const float* pn    = (const float*)d_in[0];
    const float* pca   = (const float*)d_in[1];
    const float* pc    = (const float*)d_in[2];
    const int*   rtype = (const int*)  d_in[3];
    /* batch d_in[4] unused */
    const int*   eidx  = (const int*)  d_in[5];
    const float* resemb= (const float*)d_in[6];
    const float* bbemb = (const float*)d_in[7];
    const float* ligW  = (const float*)d_in[8];
    const float* ligb  = (const float*)d_in[9];
    const float* bbW   = (const float*)d_in[10];
    const float* bbB   = (const float*)d_in[11];
    const float* e1W   = (const float*)d_in[12];
    const float* e1B   = (const float*)d_in[13];
    const float* e2aW  = (const float*)d_in[14];
    const float* e2aB  = (const float*)d_in[15];
    const float* e2bW  = (const float*)d_in[16];
    const float* e2bB  = (const float*)d_in[17];
    const float* sc1W  = (const float*)d_in[18];
    const float* sc1B  = (const float*)d_in[19];
    const float* sc2W  = (const float*)d_in[20];
    const float* sc2B  = (const float*)d_in[21];
    float* out = (float*)d_out;

    size_t smem_res = SMEM_RES_FLOATS * sizeof(float);
    cudaFuncSetAttribute(k_res, cudaFuncAttributeMaxDynamicSharedMemorySize, (int)smem_res);

    k_zero<<<512, 256>>>();
    k_prep_pos<<<(NRES + 127) / 128, 128>>>(pn, pca, pc);
    k_prep_w<<<(192 * EMB + 255) / 256, 256>>>(ligW, ligb, bbemb);
    k_prep_wd<<<(128 * 256 + 255) / 256, 256>>>(bbW, e1W, e2aW, e2bW);
    k_edge<<<NEDGE / 256, 256>>>(eidx);
    k_lig<<<NODES / 32, 128>>>(bbemb);
    k_res<<<NRES / TRES, 128, smem_res>>>(pn, pca, pc, rtype, resemb,
                                          bbB, e1B, e2aB, e2bB,
                                          sc1W, sc1B, sc2W, sc2B, out);
}

// round 3
// speedup vs baseline: 1.3707x; 1.0430x over previous
#include <cuda_runtime.h>
#include <math.h>

#define NRES  16384
#define NODES 49152
#define NEDGE 786432
#define EMB   128
#define NRAD  64
#define TRES  16
#define STRF  36   // activation column stride in floats
#define STRD  18   // in u64
#define STRV  9    // in ulonglong2

typedef unsigned long long u64;

__device__ __forceinline__ u64 pk2(float lo, float hi) {
    u64 r; asm("mov.b64 %0,{%1,%2};" : "=l"(r) : "f"(lo), "f"(hi)); return r;
}
__device__ __forceinline__ u64 pkw(float w) {
    u64 r; asm("mov.b64 %0,{%1,%1};" : "=l"(r) : "f"(w)); return r;
}
__device__ __forceinline__ void up2(u64 a, float& lo, float& hi) {
    asm("mov.b64 {%0,%1},%2;" : "=f"(lo), "=f"(hi) : "l"(a));
}
__device__ __forceinline__ u64 ff2(u64 a, u64 b, u64 c) {
    u64 d; asm("fma.rn.f32x2 %0,%1,%2,%3;" : "=l"(d) : "l"(a), "l"(b), "l"(c)); return d;
}

// ---------------- device scratch ----------------
__device__ float4 g_pos[NODES];
__device__ float  g_accR[NODES * 3 * NRAD];
__device__ float  g_cnt[NODES * 3];
__device__ float  g_lig[NODES * EMB];
__device__ float  g_bp[3 * EMB];
__device__ float  g_Wp[192 * EMB];   // fused lig weights (float, not duplicated)

// ---------------- merged init: zero accumulators + pack pos + fuse weights ----------------
__global__ void __launch_bounds__(256) k_init(const float* __restrict__ pn,
                                              const float* __restrict__ pca,
                                              const float* __restrict__ pc,
                                              const float* __restrict__ ligW,
                                              const float* __restrict__ ligb,
                                              const float* __restrict__ bbemb) {
    int idx = blockIdx.x * blockDim.x + threadIdx.x;
    int stride = gridDim.x * blockDim.x;
    float4 z = make_float4(0.f, 0.f, 0.f, 0.f);
    const int n1 = (NODES * 3 * NRAD) / 4;
    float4* a = reinterpret_cast<float4*>(g_accR);
    for (int i = idx; i < n1; i += stride) a[i] = z;
    const int n2 = (NODES * 3) / 4;
    float4* cvec = reinterpret_cast<float4*>(g_cnt);
    for (int i = idx; i < n2; i += stride) cvec[i] = z;

    if (idx < NRES) {
        int n = idx;
        g_pos[3 * n + 0] = make_float4(pn[3 * n], pn[3 * n + 1], pn[3 * n + 2], 0.f);
        g_pos[3 * n + 1] = make_float4(pca[3 * n], pca[3 * n + 1], pca[3 * n + 2], 0.f);
        g_pos[3 * n + 2] = make_float4(pc[3 * n], pc[3 * n + 1], pc[3 * n + 2], 0.f);
    }
    if (idx < 192 * EMB) {
        int c = idx & 127;
        int kk = idx >> 7;
        int t = kk / NRAD;
        int k = kk - t * NRAD;
        g_Wp[idx] = ligW[k * EMB + c] * bbemb[t * EMB + c];
    }
    if (idx < 3 * EMB) g_bp[idx] = ligb[idx & 127] * bbemb[idx];
}

// ---------------- edge phase with distance cutoff ----------------
__global__ void __launch_bounds__(256) k_edge(const int* __restrict__ ei) {
    int e = blockIdx.x * blockDim.x + threadIdx.x;
    if (e >= NEDGE) return;
    int i = ei[e];
    int j = ei[NEDGE + e];
    float4 pi = g_pos[i];
    float4 pj = g_pos[j];
    float dx = pi.x - pj.x, dy = pi.y - pj.y, dz = pi.z - pj.z;
    float d2 = dx * dx + dy * dy + dz * dz;
    int tj = j % 3;
    atomicAdd(&g_cnt[i * 3 + tj], 1.0f);
    if (d2 < 44.0f) {
        float d = sqrtf(d2);
        float* base = &g_accR[(i * 3 + tj) * NRAD];
        const float step = 5.0f / 63.0f;
#pragma unroll
        for (int k = 0; k < NRAD; k += 4) {
            float t0 = d - (k + 0) * step;
            float t1 = d - (k + 1) * step;
            float t2 = d - (k + 2) * step;
            float t3 = d - (k + 3) * step;
            float v0 = __expf(-10.0f * t0 * t0);
            float v1 = __expf(-10.0f * t1 * t1);
            float v2 = __expf(-10.0f * t2 * t2);
            float v3 = __expf(-10.0f * t3 * t3);
            unsigned long long gaddr = (unsigned long long)__cvta_generic_to_global(base + k);
            asm volatile("red.global.add.v4.f32 [%0], {%1,%2,%3,%4};"
                         :: "l"(gaddr), "f"(v0), "f"(v1), "f"(v2), "f"(v3) : "memory");
        }
    }
}

// ---------------- FMA2 GEMM helpers (float weights, packed on the fly) ----------------
template<int K>
__device__ __forceinline__ void gemm8(const ulonglong2* __restrict__ X, int half,
                                      const float* __restrict__ W, int ldw,
                                      int c0, int c1, u64* aA, u64* aB) {
#pragma unroll
    for (int i = 0; i < 8; i++) { aA[i] = 0ull; aB[i] = 0ull; }
    const ulonglong2* xp = X + 4 * half;
#pragma unroll 2
    for (int k = 0; k < K; k++) {
        u64 w0 = pkw(__ldg(&W[k * ldw + c0]));
        u64 w1 = pkw(__ldg(&W[k * ldw + c1]));
#pragma unroll
        for (int r2 = 0; r2 < 4; r2++) {
            ulonglong2 x = xp[k * STRV + r2];
            aA[2 * r2]     = ff2(x.x, w0, aA[2 * r2]);
            aA[2 * r2 + 1] = ff2(x.y, w0, aA[2 * r2 + 1]);
            aB[2 * r2]     = ff2(x.x, w1, aB[2 * r2]);
            aB[2 * r2 + 1] = ff2(x.y, w1, aB[2 * r2 + 1]);
        }
    }
}

template<int K>
__device__ __forceinline__ void gemm16(const ulonglong2* __restrict__ X,
                                       const float* __restrict__ W, int ldw,
                                       int c0, int c1, u64* aA, u64* aB) {
#pragma unroll
    for (int i = 0; i < 16; i++) { aA[i] = 0ull; aB[i] = 0ull; }
#pragma unroll 2
    for (int k = 0; k < K; k++) {
        u64 w0 = pkw(__ldg(&W[k * ldw + c0]));
        u64 w1 = pkw(__ldg(&W[k * ldw + c1]));
#pragma unroll
        for (int r2 = 0; r2 < 8; r2++) {
            ulonglong2 x = X[k * STRV + r2];
            aA[2 * r2]     = ff2(x.x, w0, aA[2 * r2]);
            aA[2 * r2 + 1] = ff2(x.y, w0, aA[2 * r2 + 1]);
            aB[2 * r2]     = ff2(x.x, w1, aB[2 * r2]);
            aB[2 * r2 + 1] = ff2(x.y, w1, aB[2 * r2 + 1]);
        }
    }
}

// ---------------- node phase ----------------
__global__ void __launch_bounds__(128) k_lig(const float* __restrict__ bbemb) {
    __shared__ __align__(16) float shT[192 * STRF];
    __shared__ float shc[96];
    int tid = threadIdx.x;
    int i0 = blockIdx.x * 32;
    const float4* gR = (const float4*)(g_accR + (size_t)i0 * 192);
    for (int q = tid; q < 1536; q += 128) {
        int r = q / 48, k4 = q - 48 * r;
        float4 v = gR[q];
        int kb = 4 * k4;
        shT[(kb + 0) * STRF + r] = v.x;
        shT[(kb + 1) * STRF + r] = v.y;
        shT[(kb + 2) * STRF + r] = v.z;
        shT[(kb + 3) * STRF + r] = v.w;
    }
    if (tid < 96) shc[tid] = g_cnt[i0 * 3 + tid];
    __syncthreads();

    int c0 = tid & 63, half = tid >> 6, c1 = c0 + 64;
    u64 aA[8], aB[8];
    gemm8<192>((const ulonglong2*)shT, half, g_Wp, 128, c0, c1, aA, aB);

    float b00 = g_bp[c0], b01 = g_bp[128 + c0], b02 = g_bp[256 + c0];
    float b10 = g_bp[c1], b11 = g_bp[128 + c1], b12 = g_bp[256 + c1];
    float x00 = bbemb[c0], x01 = bbemb[128 + c0], x02 = bbemb[256 + c0];
    float x10 = bbemb[c1], x11 = bbemb[128 + c1], x12 = bbemb[256 + c1];
#pragma unroll
    for (int jj = 0; jj < 8; jj++) {
        int rp = 8 * half + jj;
        int r0 = 2 * rp, r1 = r0 + 1;
        int v0 = i0 + r0, v1 = i0 + r1;
        float ca0 = shc[r0 * 3 + 0], ca1 = shc[r0 * 3 + 1], ca2 = shc[r0 * 3 + 2];
        float cb0 = shc[r1 * 3 + 0], cb1 = shc[r1 * 3 + 1], cb2 = shc[r1 * 3 + 2];
        float dga = ca0 + ca1 + ca2, dgb = cb0 + cb1 + cb2;
        int a0 = v0 % 3, a1 = v1 % 3;
        float y0, y1;
        up2(aA[jj], y0, y1);
        float xs0 = (a0 == 0) ? x00 : ((a0 == 1) ? x01 : x02);
        float xs1 = (a1 == 0) ? x00 : ((a1 == 1) ? x01 : x02);
        g_lig[v0 * EMB + c0] = fmaf(dga, xs0, y0) + ca0 * b00 + ca1 * b01 + ca2 * b02;
        g_lig[v1 * EMB + c0] = fmaf(dgb, xs1, y1) + cb0 * b00 + cb1 * b01 + cb2 * b02;
        up2(aB[jj], y0, y1);
        float xt0 = (a0 == 0) ? x10 : ((a0 == 1) ? x11 : x12);
        float xt1 = (a1 == 0) ? x10 : ((a1 == 1) ? x11 : x12);
        g_lig[v0 * EMB + c1] = fmaf(dga, xt0, y0) + ca0 * b10 + ca1 * b11 + ca2 * b12;
        g_lig[v1 * EMB + c1] = fmaf(dgb, xt1, y1) + cb0 * b10 + cb1 * b11 + cb2 * b12;
    }
}

// ---------------- residue phase ----------------
#define SMEM_RES_FLOATS (18432 + 384)

__global__ void __launch_bounds__(128) k_res(
    const float* __restrict__ pn, const float* __restrict__ pca, const float* __restrict__ pc,
    const int* __restrict__ rtype, const float* __restrict__ resemb,
    const float* __restrict__ bbW, const float* __restrict__ bbB,
    const float* __restrict__ e1W, const float* __restrict__ e1B,
    const float* __restrict__ e2aW, const float* __restrict__ e2aB,
    const float* __restrict__ e2bW, const float* __restrict__ e2bB,
    const float* __restrict__ sc1W, const float* __restrict__ sc1B,
    const float* __restrict__ sc2W, const float* __restrict__ sc2B,
    float* __restrict__ out)
{
    extern __shared__ float sm[];
    float* bufA = sm;                      // 4608 (rbf then s1)
    float* bufB = sm + 4608;               // 4608 (g)
    float* bufC = sm + 9216;               // 9216 (m)
    float* sh_p = sm + 18432;              // 96
    float* sh_q = sh_p + 96;               // 96
    float* sh_d = sh_q + 96;               // 32
    float* sh_w1 = sh_d + 32;              // 96
    float* sh_b1s = sh_w1 + 96;            // 32
    float* sh_w2 = sh_b1s + 32;            // 32
    const ulonglong2* bufA2 = reinterpret_cast<const ulonglong2*>(bufA);
    const ulonglong2* bufB2 = reinterpret_cast<const ulonglong2*>(bufB);
    const ulonglong2* bufC2 = reinterpret_cast<const ulonglong2*>(bufC);
    u64* bufAD = reinterpret_cast<u64*>(bufA);
    u64* bufBD = reinterpret_cast<u64*>(bufB);
    u64* bufCD = reinterpret_cast<u64*>(bufC);

    int tid = threadIdx.x;
    int n0 = blockIdx.x * TRES;
    int c0 = tid & 63, half = tid >> 6, c1 = c0 + 64;

    if (tid < 96) sh_w1[tid] = sc1W[tid];
    if (tid < 32) { sh_b1s[tid] = sc1B[tid]; sh_w2[tid] = sc2W[tid]; }
    float b2s = sc2B[0];

    if (tid < TRES) {
        int n = n0 + tid;
        float nx = pn[3 * n], ny = pn[3 * n + 1], nz = pn[3 * n + 2];
        float ax = pca[3 * n], ay = pca[3 * n + 1], az = pca[3 * n + 2];
        float cx = pc[3 * n], cy = pc[3 * n + 1], cz = pc[3 * n + 2];
        float v1x = ax - nx, v1y = ay - ny, v1z = az - nz;
        float d1 = sqrtf(v1x * v1x + v1y * v1y + v1z * v1z);
        float i1 = 1.0f / fmaxf(d1, 1e-8f);
        float f1x = v1x * i1, f1y = v1y * i1, f1z = v1z * i1;
        float v2x = cx - ax, v2y = cy - ay, v2z = cz - az;
        float d2 = sqrtf(v2x * v2x + v2y * v2y + v2z * v2z);
        float i2 = 1.0f / fmaxf(d2, 1e-8f);
        float f2x = v2x * i2, f2y = v2y * i2, f2z = v2z * i2;
        float crx = f1y * f2z - f1z * f2y;
        float cry = f1z * f2x - f1x * f2z;
        float crz = f1x * f2y - f1y * f2x;
        float dc = sqrtf(crx * crx + cry * cry + crz * crz);
        float i3 = 1.0f / fmaxf(dc, 1e-8f);
        float f3x = crx * i3, f3y = cry * i3, f3z = crz * i3;

        int r0 = 2 * tid;
        sh_d[r0] = d1;
        sh_d[r0 + 1] = d2;
        sh_p[r0 * 3 + 0] = v1x * f1x + v1y * f1y + v1z * f1z;
        sh_p[r0 * 3 + 1] = v1x * f2x + v1y * f2y + v1z * f2z;
        sh_p[r0 * 3 + 2] = v1x * f3x + v1y * f3y + v1z * f3z;
        sh_p[(r0 + 1) * 3 + 0] = v2x * f1x + v2y * f1y + v2z * f1z;
        sh_p[(r0 + 1) * 3 + 1] = v2x * f2x + v2y * f2y + v2z * f2z;
        sh_p[(r0 + 1) * 3 + 2] = v2x * f3x + v2y * f3y + v2z * f3z;
        float q0 = f1x + f1y + f1z;
        float q1 = f2x + f2y + f2z;
        float q2 = f3x + f3y + f3z;
        sh_q[r0 * 3 + 0] = q0; sh_q[r0 * 3 + 1] = q1; sh_q[r0 * 3 + 2] = q2;
        sh_q[(r0 + 1) * 3 + 0] = q0; sh_q[(r0 + 1) * 3 + 1] = q1; sh_q[(r0 + 1) * 3 + 2] = q2;
    }
    __syncthreads();

    {
        int k = tid & 63;
        int rh = tid >> 6;
        float mu = (float)k * (5.0f / 63.0f);
#pragma unroll
        for (int r = rh; r < 32; r += 2) {
            float t = sh_d[r] - mu;
            bufA[k * STRF + r] = __expf(-10.0f * t * t);
        }
    }
    __syncthreads();

    {
        u64 hA[8], hB[8];
        gemm8<64>(bufA2, half, bbW, 128, c0, c1, hA, hB);
        float bb0 = bbB[c0], bb1 = bbB[c1];
#pragma unroll
        for (int jj = 0; jj < 8; jj++) {
            int rp = 8 * half + jj;
            int n = n0 + rp;
            const float* L = g_lig + (size_t)(3 * n) * EMB;
            float u0a = L[c0], u1a = L[EMB + c0], u2a = L[2 * EMB + c0];
            float u0b = L[c1], u1b = L[EMB + c1], u2b = L[2 * EMB + c1];
            float h0, h1;
            up2(hA[jj], h0, h1);
            bufBD[c0 * STRD + rp] = pk2((h0 + bb0) * u0a * u1a, (h1 + bb0) * u1a * u2a);
            up2(hB[jj], h0, h1);
            bufBD[c1 * STRD + rp] = pk2((h0 + bb1) * u0b * u1b, (h1 + bb1) * u1b * u2b);
        }
    }
    __syncthreads();

    {
        u64 hA[8], hB[8];
        gemm8<128>(bufB2, half, e1W, 128, c0, c1, hA, hB);
        float b1c0 = e1B[c0], b1c1 = e1B[c1];
#pragma unroll 1
        for (int jj = 0; jj < 8; jj++) {
            int rp = 8 * half + jj;
            int r0 = 2 * rp, r1 = r0 + 1;
            float p00 = sh_p[r0 * 3 + 0], p01 = sh_p[r0 * 3 + 1], p02 = sh_p[r0 * 3 + 2];
            float p10 = sh_p[r1 * 3 + 0], p11 = sh_p[r1 * 3 + 1], p12 = sh_p[r1 * 3 + 2];
            float q0 = sh_q[r0 * 3 + 0], q1 = sh_q[r0 * 3 + 1], q2 = sh_q[r0 * 3 + 2];
            float hA0, hA1, hB0, hB1;
            up2(hA[jj], hA0, hA1);
            up2(hB[jj], hB0, hB1);
            float sA0x = hA0 * p00 + b1c0 * q0, sA0y = hA0 * p01 + b1c0 * q1, sA0z = hA0 * p02 + b1c0 * q2;
            float sA1x = hA1 * p10 + b1c0 * q0, sA1y = hA1 * p11 + b1c0 * q1, sA1z = hA1 * p12 + b1c0 * q2;
            float sB0x = hB0 * p00 + b1c1 * q0, sB0y = hB0 * p01 + b1c1 * q1, sB0z = hB0 * p02 + b1c1 * q2;
            float sB1x = hB1 * p10 + b1c1 * q0, sB1y = hB1 * p11 + b1c1 * q1, sB1z = hB1 * p12 + b1c1 * q2;
            float zA0 = 0.f, zA1 = 0.f, zB0 = 0.f, zB1 = 0.f;
#pragma unroll 1
            for (int m = 0; m < 32; m++) {
                float w0 = sh_w1[m], w1 = sh_w1[32 + m], w2 = sh_w1[64 + m];
                float bb = sh_b1s[m], wo = sh_w2[m];
                float t0 = fmaf(sA0x, w0, fmaf(sA0y, w1, fmaf(sA0z, w2, bb)));
                float t1 = fmaf(sA1x, w0, fmaf(sA1y, w1, fmaf(sA1z, w2, bb)));
                float t2 = fmaf(sB0x, w0, fmaf(sB0y, w1, fmaf(sB0z, w2, bb)));
                float t3 = fmaf(sB1x, w0, fmaf(sB1y, w1, fmaf(sB1z, w2, bb)));
                float g0 = __fdividef(t0, 1.0f + __expf(-t0));
                float g1 = __fdividef(t1, 1.0f + __expf(-t1));
                float g2 = __fdividef(t2, 1.0f + __expf(-t2));
                float g3 = __fdividef(t3, 1.0f + __expf(-t3));
                zA0 = fmaf(g0, wo, zA0);
                zA1 = fmaf(g1, wo, zA1);
                zB0 = fmaf(g2, wo, zB0);
                zB1 = fmaf(g3, wo, zB1);
            }
            bufAD[c0 * STRD + rp] = pk2(zA0 + b2s + sA0x, zA1 + b2s + sA1x);
            bufAD[c1 * STRD + rp] = pk2(zB0 + b2s + sB0x, zB1 + b2s + sB1x);
        }
    }
    __syncthreads();

    {
        u64 mA[16], mB[16];
        gemm16<128>(bufA2, e2aW, 256, tid, tid + 128, mA, mB);
        float ba0 = e2aB[tid], ba1 = e2aB[tid + 128];
#pragma unroll
        for (int rp = 0; rp < 16; rp++) {
            float x0, x1;
            up2(mA[rp], x0, x1);
            bufCD[tid * STRD + rp] = pk2(fmaxf(x0 + ba0, 0.f), fmaxf(x1 + ba0, 0.f));
            up2(mB[rp], x0, x1);
            bufCD[(tid + 128) * STRD + rp] = pk2(fmaxf(x0 + ba1, 0.f), fmaxf(x1 + ba1, 0.f));
        }
    }
    __syncthreads();

    {
        u64 yA[8], yB[8];
        gemm8<256>(bufC2, half, e2bW, 128, c0, c1, yA, yB);
        float bb2_0 = e2bB[c0], bb2_1 = e2bB[c1];
#pragma unroll
        for (int jj = 0; jj < 8; jj++) {
            int rp = 8 * half + jj;
            int n = n0 + rp;
            int rt = rtype[n];
            float y0, y1;
            up2(yA[jj], y0, y1);
            out[n * EMB + c0] = 0.5f * (y0 + y1) + bb2_0 + resemb[rt * EMB + c0];
            up2(yB[jj], y0, y1);
            out[n * EMB + c1] = 0.5f * (y0 + y1) + bb2_1 + resemb[rt * EMB + c1];
        }
    }
}

// ---------------- launch ----------------
extern "C" void kernel_launch(void* const* d_in, const int* in_sizes, int n_in,
                              void* d_out, int out_size) {
    const float* pn    = (const float*)d_in[0];
    const float* pca   = (const float*)d_in[1];
    const float* pc    = (const float*)d_in[2];
    const int*   rtype = (const int*)  d_in[3];
    /* batch d_in[4] unused */
    const int*   eidx  = (const int*)  d_in[5];
    const float* resemb= (const float*)d_in[6];
    const float* bbemb = (const float*)d_in[7];
    const float* ligW  = (const float*)d_in[8];
    const float* ligb  = (const float*)d_in[9];
    const float* bbW   = (const float*)d_in[10];
    const float* bbB   = (const float*)d_in[11];
    const float* e1W   = (const float*)d_in[12];
    const float* e1B   = (const float*)d_in[13];
    const float* e2aW  = (const float*)d_in[14];
    const float* e2aB  = (const float*)d_in[15];
    const float* e2bW  = (const float*)d_in[16];
    const float* e2bB  = (const float*)d_in[17];
    const float* sc1W  = (const float*)d_in[18];
    const float* sc1B  = (const float*)d_in[19];
    const float* sc2W  = (const float*)d_in[20];
    const float* sc2B  = (const float*)d_in[21];
    float* out = (float*)d_out;

    size_t smem_res = SMEM_RES_FLOATS * sizeof(float);
    cudaFuncSetAttribute(k_res, cudaFuncAttributeMaxDynamicSharedMemorySize, (int)smem_res);

    k_init<<<2048, 256>>>(pn, pca, pc, ligW, ligb, bbemb);
    k_edge<<<NEDGE / 256, 256>>>(eidx);
    k_lig<<<NODES / 32, 128>>>(bbemb);
    k_res<<<NRES / TRES, 128, smem_res>>>(pn, pca, pc, rtype, resemb,
                                          bbW, bbB, e1W, e1B,
                                          e2aW, e2aB, e2bW, e2bB,
                                          sc1W, sc1B, sc2W, sc2B, out);
}

// round 4
// speedup vs baseline: 1.3719x; 1.0009x over previous
#include <cuda_runtime.h>
#include <math.h>

#define NRES  16384
#define NODES 49152
#define NEDGE 786432
#define EMB   128
#define NRAD  64
#define TRES  16
#define STRF  36   // activation column stride in floats
#define STRD  18   // in u64
#define STRV  9    // in ulonglong2

typedef unsigned long long u64;

__device__ __forceinline__ u64 pk2(float lo, float hi) {
    u64 r; asm("mov.b64 %0,{%1,%2};" : "=l"(r) : "f"(lo), "f"(hi)); return r;
}
__device__ __forceinline__ u64 pkw(float w) {
    u64 r; asm("mov.b64 %0,{%1,%1};" : "=l"(r) : "f"(w)); return r;
}
__device__ __forceinline__ void up2(u64 a, float& lo, float& hi) {
    asm("mov.b64 {%0,%1},%2;" : "=f"(lo), "=f"(hi) : "l"(a));
}
__device__ __forceinline__ u64 ff2(u64 a, u64 b, u64 c) {
    u64 d; asm("fma.rn.f32x2 %0,%1,%2,%3;" : "=l"(d) : "l"(a), "l"(b), "l"(c)); return d;
}

// ---------------- device scratch ----------------
__device__ float4 g_pos[NODES];
__device__ float  g_accR[NODES * 3 * NRAD];
__device__ float  g_cnt[NODES * 3];
__device__ float  g_lig[NODES * EMB];
__device__ float  g_bp[3 * EMB];
__device__ float  g_Wp[192 * EMB];

// ---------------- merged init ----------------
__global__ void __launch_bounds__(256) k_init(const float* __restrict__ pn,
                                              const float* __restrict__ pca,
                                              const float* __restrict__ pc,
                                              const float* __restrict__ ligW,
                                              const float* __restrict__ ligb,
                                              const float* __restrict__ bbemb) {
    int idx = blockIdx.x * blockDim.x + threadIdx.x;
    int stride = gridDim.x * blockDim.x;
    float4 z = make_float4(0.f, 0.f, 0.f, 0.f);
    const int n1 = (NODES * 3 * NRAD) / 4;
    float4* a = reinterpret_cast<float4*>(g_accR);
    for (int i = idx; i < n1; i += stride) a[i] = z;
    const int n2 = (NODES * 3) / 4;
    float4* cvec = reinterpret_cast<float4*>(g_cnt);
    for (int i = idx; i < n2; i += stride) cvec[i] = z;

    if (idx < NRES) {
        int n = idx;
        g_pos[3 * n + 0] = make_float4(pn[3 * n], pn[3 * n + 1], pn[3 * n + 2], 0.f);
        g_pos[3 * n + 1] = make_float4(pca[3 * n], pca[3 * n + 1], pca[3 * n + 2], 0.f);
        g_pos[3 * n + 2] = make_float4(pc[3 * n], pc[3 * n + 1], pc[3 * n + 2], 0.f);
    }
    if (idx < 192 * EMB) {
        int c = idx & 127;
        int kk = idx >> 7;
        int t = kk / NRAD;
        int k = kk - t * NRAD;
        g_Wp[idx] = ligW[k * EMB + c] * bbemb[t * EMB + c];
    }
    if (idx < 3 * EMB) g_bp[idx] = ligb[idx & 127] * bbemb[idx];
}

// ---------------- edge phase with distance cutoff ----------------
__global__ void __launch_bounds__(256) k_edge(const int* __restrict__ ei) {
    int e = blockIdx.x * blockDim.x + threadIdx.x;
    if (e >= NEDGE) return;
    int i = ei[e];
    int j = ei[NEDGE + e];
    float4 pi = g_pos[i];
    float4 pj = g_pos[j];
    float dx = pi.x - pj.x, dy = pi.y - pj.y, dz = pi.z - pj.z;
    float d2 = dx * dx + dy * dy + dz * dz;
    int tj = j % 3;
    atomicAdd(&g_cnt[i * 3 + tj], 1.0f);
    if (d2 < 44.0f) {
        float d = sqrtf(d2);
        float* base = &g_accR[(i * 3 + tj) * NRAD];
        const float step = 5.0f / 63.0f;
#pragma unroll
        for (int k = 0; k < NRAD; k += 4) {
            float t0 = d - (k + 0) * step;
            float t1 = d - (k + 1) * step;
            float t2 = d - (k + 2) * step;
            float t3 = d - (k + 3) * step;
            float v0 = __expf(-10.0f * t0 * t0);
            float v1 = __expf(-10.0f * t1 * t1);
            float v2 = __expf(-10.0f * t2 * t2);
            float v3 = __expf(-10.0f * t3 * t3);
            unsigned long long gaddr = (unsigned long long)__cvta_generic_to_global(base + k);
            asm volatile("red.global.add.v4.f32 [%0], {%1,%2,%3,%4};"
                         :: "l"(gaddr), "f"(v0), "f"(v1), "f"(v2), "f"(v3) : "memory");
        }
    }
}

// ---------------- FMA2 GEMM helper ----------------
// 8 row-pairs (half of 32 rows), 2 output channels. ACC=true accumulates into aA/aB.
template<int K, bool ACC>
__device__ __forceinline__ void gemm8(const ulonglong2* __restrict__ X, int half,
                                      const float* __restrict__ W, int ldw,
                                      int c0, int c1, u64* aA, u64* aB) {
    if (!ACC) {
#pragma unroll
        for (int i = 0; i < 8; i++) { aA[i] = 0ull; aB[i] = 0ull; }
    }
    const ulonglong2* xp = X + 4 * half;
#pragma unroll 2
    for (int k = 0; k < K; k++) {
        u64 w0 = pkw(__ldg(&W[k * ldw + c0]));
        u64 w1 = pkw(__ldg(&W[k * ldw + c1]));
#pragma unroll
        for (int r2 = 0; r2 < 4; r2++) {
            ulonglong2 x = xp[k * STRV + r2];
            aA[2 * r2]     = ff2(x.x, w0, aA[2 * r2]);
            aA[2 * r2 + 1] = ff2(x.y, w0, aA[2 * r2 + 1]);
            aB[2 * r2]     = ff2(x.x, w1, aB[2 * r2]);
            aB[2 * r2 + 1] = ff2(x.y, w1, aB[2 * r2 + 1]);
        }
    }
}

// ---------------- node phase ----------------
__global__ void __launch_bounds__(128) k_lig(const float* __restrict__ bbemb) {
    __shared__ __align__(16) float shT[192 * STRF];
    __shared__ float shc[96];
    int tid = threadIdx.x;
    int i0 = blockIdx.x * 32;
    const float4* gR = (const float4*)(g_accR + (size_t)i0 * 192);
    for (int q = tid; q < 1536; q += 128) {
        int r = q / 48, k4 = q - 48 * r;
        float4 v = gR[q];
        int kb = 4 * k4;
        shT[(kb + 0) * STRF + r] = v.x;
        shT[(kb + 1) * STRF + r] = v.y;
        shT[(kb + 2) * STRF + r] = v.z;
        shT[(kb + 3) * STRF + r] = v.w;
    }
    if (tid < 96) shc[tid] = g_cnt[i0 * 3 + tid];
    __syncthreads();

    int c0 = tid & 63, half = tid >> 6, c1 = c0 + 64;
    u64 aA[8], aB[8];
    gemm8<192, false>((const ulonglong2*)shT, half, g_Wp, 128, c0, c1, aA, aB);

    float b00 = g_bp[c0], b01 = g_bp[128 + c0], b02 = g_bp[256 + c0];
    float b10 = g_bp[c1], b11 = g_bp[128 + c1], b12 = g_bp[256 + c1];
    float x00 = bbemb[c0], x01 = bbemb[128 + c0], x02 = bbemb[256 + c0];
    float x10 = bbemb[c1], x11 = bbemb[128 + c1], x12 = bbemb[256 + c1];
#pragma unroll
    for (int jj = 0; jj < 8; jj++) {
        int rp = 8 * half + jj;
        int r0 = 2 * rp, r1 = r0 + 1;
        int v0 = i0 + r0, v1 = i0 + r1;
        float ca0 = shc[r0 * 3 + 0], ca1 = shc[r0 * 3 + 1], ca2 = shc[r0 * 3 + 2];
        float cb0 = shc[r1 * 3 + 0], cb1 = shc[r1 * 3 + 1], cb2 = shc[r1 * 3 + 2];
        float dga = ca0 + ca1 + ca2, dgb = cb0 + cb1 + cb2;
        int a0 = v0 % 3, a1 = v1 % 3;
        float y0, y1;
        up2(aA[jj], y0, y1);
        float xs0 = (a0 == 0) ? x00 : ((a0 == 1) ? x01 : x02);
        float xs1 = (a1 == 0) ? x00 : ((a1 == 1) ? x01 : x02);
        g_lig[v0 * EMB + c0] = fmaf(dga, xs0, y0) + ca0 * b00 + ca1 * b01 + ca2 * b02;
        g_lig[v1 * EMB + c0] = fmaf(dgb, xs1, y1) + cb0 * b00 + cb1 * b01 + cb2 * b02;
        up2(aB[jj], y0, y1);
        float xt0 = (a0 == 0) ? x10 : ((a0 == 1) ? x11 : x12);
        float xt1 = (a1 == 0) ? x10 : ((a1 == 1) ? x11 : x12);
        g_lig[v0 * EMB + c1] = fmaf(dga, xt0, y0) + ca0 * b10 + ca1 * b11 + ca2 * b12;
        g_lig[v1 * EMB + c1] = fmaf(dgb, xt1, y1) + cb0 * b10 + cb1 * b11 + cb2 * b12;
    }
}

// ---------------- residue phase (chunked, 38.4KB smem) ----------------
#define SMEM_RES_FLOATS (4608 + 4608 + 384)

__global__ void __launch_bounds__(128, 5) k_res(
    const float* __restrict__ pn, const float* __restrict__ pca, const float* __restrict__ pc,
    const int* __restrict__ rtype, const float* __restrict__ resemb,
    const float* __restrict__ bbW, const float* __restrict__ bbB,
    const float* __restrict__ e1W, const float* __restrict__ e1B,
    const float* __restrict__ e2aW, const float* __restrict__ e2aB,
    const float* __restrict__ e2bW, const float* __restrict__ e2bB,
    const float* __restrict__ sc1W, const float* __restrict__ sc1B,
    const float* __restrict__ sc2W, const float* __restrict__ sc2B,
    float* __restrict__ out)
{
    extern __shared__ float sm[];
    float* bufA = sm;                      // 4608 (rbf then s1)
    float* bufB = sm + 4608;               // 4608 (g, then m-chunks)
    float* sh_p = sm + 9216;               // 96
    float* sh_q = sh_p + 96;               // 96
    float* sh_d = sh_q + 96;               // 32
    float* sh_w1 = sh_d + 32;              // 96
    float* sh_b1s = sh_w1 + 96;            // 32
    float* sh_w2 = sh_b1s + 32;            // 32
    const ulonglong2* bufA2 = reinterpret_cast<const ulonglong2*>(bufA);
    const ulonglong2* bufB2 = reinterpret_cast<const ulonglong2*>(bufB);
    u64* bufAD = reinterpret_cast<u64*>(bufA);
    u64* bufBD = reinterpret_cast<u64*>(bufB);

    int tid = threadIdx.x;
    int n0 = blockIdx.x * TRES;
    int c0 = tid & 63, half = tid >> 6, c1 = c0 + 64;

    if (tid < 96) sh_w1[tid] = sc1W[tid];
    if (tid < 32) { sh_b1s[tid] = sc1B[tid]; sh_w2[tid] = sc2W[tid]; }
    float b2s = sc2B[0];

    if (tid < TRES) {
        int n = n0 + tid;
        float nx = pn[3 * n], ny = pn[3 * n + 1], nz = pn[3 * n + 2];
        float ax = pca[3 * n], ay = pca[3 * n + 1], az = pca[3 * n + 2];
        float cx = pc[3 * n], cy = pc[3 * n + 1], cz = pc[3 * n + 2];
        float v1x = ax - nx, v1y = ay - ny, v1z = az - nz;
        float d1 = sqrtf(v1x * v1x + v1y * v1y + v1z * v1z);
        float i1 = 1.0f / fmaxf(d1, 1e-8f);
        float f1x = v1x * i1, f1y = v1y * i1, f1z = v1z * i1;
        float v2x = cx - ax, v2y = cy - ay, v2z = cz - az;
        float d2 = sqrtf(v2x * v2x + v2y * v2y + v2z * v2z);
        float i2 = 1.0f / fmaxf(d2, 1e-8f);
        float f2x = v2x * i2, f2y = v2y * i2, f2z = v2z * i2;
        float crx = f1y * f2z - f1z * f2y;
        float cry = f1z * f2x - f1x * f2z;
        float crz = f1x * f2y - f1y * f2x;
        float dc = sqrtf(crx * crx + cry * cry + crz * crz);
        float i3 = 1.0f / fmaxf(dc, 1e-8f);
        float f3x = crx * i3, f3y = cry * i3, f3z = crz * i3;

        int r0 = 2 * tid;
        sh_d[r0] = d1;
        sh_d[r0 + 1] = d2;
        sh_p[r0 * 3 + 0] = v1x * f1x + v1y * f1y + v1z * f1z;
        sh_p[r0 * 3 + 1] = v1x * f2x + v1y * f2y + v1z * f2z;
        sh_p[r0 * 3 + 2] = v1x * f3x + v1y * f3y + v1z * f3z;
        sh_p[(r0 + 1) * 3 + 0] = v2x * f1x + v2y * f1y + v2z * f1z;
        sh_p[(r0 + 1) * 3 + 1] = v2x * f2x + v2y * f2y + v2z * f2z;
        sh_p[(r0 + 1) * 3 + 2] = v2x * f3x + v2y * f3y + v2z * f3z;
        float q0 = f1x + f1y + f1z;
        float q1 = f2x + f2y + f2z;
        float q2 = f3x + f3y + f3z;
        sh_q[r0 * 3 + 0] = q0; sh_q[r0 * 3 + 1] = q1; sh_q[r0 * 3 + 2] = q2;
        sh_q[(r0 + 1) * 3 + 0] = q0; sh_q[(r0 + 1) * 3 + 1] = q1; sh_q[(r0 + 1) * 3 + 2] = q2;
    }
    __syncthreads();

    // ---- rbf, column-major ----
    {
        int k = tid & 63;
        int rh = tid >> 6;
        float mu = (float)k * (5.0f / 63.0f);
#pragma unroll
        for (int r = rh; r < 32; r += 2) {
            float t = sh_d[r] - mu;
            bufA[k * STRF + r] = __expf(-10.0f * t * t);
        }
    }
    __syncthreads();

    // ---- radial = rbf @ bbW + b ; g = radial*u*v -> bufB ----
    {
        u64 hA[8], hB[8];
        gemm8<64, false>(bufA2, half, bbW, 128, c0, c1, hA, hB);
        float bb0 = bbB[c0], bb1 = bbB[c1];
#pragma unroll
        for (int jj = 0; jj < 8; jj++) {
            int rp = 8 * half + jj;
            int n = n0 + rp;
            const float* L = g_lig + (size_t)(3 * n) * EMB;
            float u0a = L[c0], u1a = L[EMB + c0], u2a = L[2 * EMB + c0];
            float u0b = L[c1], u1b = L[EMB + c1], u2b = L[2 * EMB + c1];
            float h0, h1;
            up2(hA[jj], h0, h1);
            bufBD[c0 * STRD + rp] = pk2((h0 + bb0) * u0a * u1a, (h1 + bb0) * u1a * u2a);
            up2(hB[jj], h0, h1);
            bufBD[c1 * STRD + rp] = pk2((h0 + bb1) * u0b * u1b, (h1 + bb1) * u1b * u2b);
        }
    }
    __syncthreads();

    // ---- h = g @ e1W ; scalarization + silu-MLP -> s1 in bufA ----
    {
        u64 hA[8], hB[8];
        gemm8<128, false>(bufB2, half, e1W, 128, c0, c1, hA, hB);
        float b1c0 = e1B[c0], b1c1 = e1B[c1];
#pragma unroll 1
        for (int jj = 0; jj < 8; jj++) {
            int rp = 8 * half + jj;
            int r0 = 2 * rp, r1 = r0 + 1;
            float p00 = sh_p[r0 * 3 + 0], p01 = sh_p[r0 * 3 + 1], p02 = sh_p[r0 * 3 + 2];
            float p10 = sh_p[r1 * 3 + 0], p11 = sh_p[r1 * 3 + 1], p12 = sh_p[r1 * 3 + 2];
            float q0 = sh_q[r0 * 3 + 0], q1 = sh_q[r0 * 3 + 1], q2 = sh_q[r0 * 3 + 2];
            float hA0, hA1, hB0, hB1;
            up2(hA[jj], hA0, hA1);
            up2(hB[jj], hB0, hB1);
            float sA0x = hA0 * p00 + b1c0 * q0, sA0y = hA0 * p01 + b1c0 * q1, sA0z = hA0 * p02 + b1c0 * q2;
            float sA1x = hA1 * p10 + b1c0 * q0, sA1y = hA1 * p11 + b1c0 * q1, sA1z = hA1 * p12 + b1c0 * q2;
            float sB0x = hB0 * p00 + b1c1 * q0, sB0y = hB0 * p01 + b1c1 * q1, sB0z = hB0 * p02 + b1c1 * q2;
            float sB1x = hB1 * p10 + b1c1 * q0, sB1y = hB1 * p11 + b1c1 * q1, sB1z = hB1 * p12 + b1c1 * q2;
            float zA0 = 0.f, zA1 = 0.f, zB0 = 0.f, zB1 = 0.f;
#pragma unroll 1
            for (int m = 0; m < 32; m++) {
                float w0 = sh_w1[m], w1 = sh_w1[32 + m], w2 = sh_w1[64 + m];
                float bb = sh_b1s[m], wo = sh_w2[m];
                float t0 = fmaf(sA0x, w0, fmaf(sA0y, w1, fmaf(sA0z, w2, bb)));
                float t1 = fmaf(sA1x, w0, fmaf(sA1y, w1, fmaf(sA1z, w2, bb)));
                float t2 = fmaf(sB0x, w0, fmaf(sB0y, w1, fmaf(sB0z, w2, bb)));
                float t3 = fmaf(sB1x, w0, fmaf(sB1y, w1, fmaf(sB1z, w2, bb)));
                float g0 = __fdividef(t0, 1.0f + __expf(-t0));
                float g1 = __fdividef(t1, 1.0f + __expf(-t1));
                float g2 = __fdividef(t2, 1.0f + __expf(-t2));
                float g3 = __fdividef(t3, 1.0f + __expf(-t3));
                zA0 = fmaf(g0, wo, zA0);
                zA1 = fmaf(g1, wo, zA1);
                zB0 = fmaf(g2, wo, zB0);
                zB1 = fmaf(g3, wo, zB1);
            }
            bufAD[c0 * STRD + rp] = pk2(zA0 + b2s + sA0x, zA1 + b2s + sA1x);
            bufAD[c1 * STRD + rp] = pk2(zB0 + b2s + sB0x, zB1 + b2s + sB1x);
        }
    }
    __syncthreads();

    // ---- fused MLP: for each 128-ch chunk, m=relu(s1@e2aW)+b in bufB, y += m@e2bW ----
    u64 yA[8], yB[8];
#pragma unroll
    for (int i = 0; i < 8; i++) { yA[i] = 0ull; yB[i] = 0ull; }
#pragma unroll 1
    for (int ch = 0; ch < 2; ch++) {
        u64 mA[8], mB[8];
        gemm8<128, false>(bufA2, half, e2aW + ch * 128, 256, c0, c1, mA, mB);
        float ba0 = e2aB[ch * 128 + c0], ba1 = e2aB[ch * 128 + c1];
#pragma unroll
        for (int jj = 0; jj < 8; jj++) {
            int rp = 8 * half + jj;
            float x0, x1;
            up2(mA[jj], x0, x1);
            bufBD[c0 * STRD + rp] = pk2(fmaxf(x0 + ba0, 0.f), fmaxf(x1 + ba0, 0.f));
            up2(mB[jj], x0, x1);
            bufBD[c1 * STRD + rp] = pk2(fmaxf(x0 + ba1, 0.f), fmaxf(x1 + ba1, 0.f));
        }
        __syncthreads();
        gemm8<128, true>(bufB2, half, e2bW + ch * 128 * 128, 128, c0, c1, yA, yB);
        __syncthreads();
    }

    // ---- epilogue ----
    {
        float bb2_0 = e2bB[c0], bb2_1 = e2bB[c1];
#pragma unroll
        for (int jj = 0; jj < 8; jj++) {
            int rp = 8 * half + jj;
            int n = n0 + rp;
            int rt = rtype[n];
            float y0, y1;
            up2(yA[jj], y0, y1);
            out[n * EMB + c0] = 0.5f * (y0 + y1) + bb2_0 + resemb[rt * EMB + c0];
            up2(yB[jj], y0, y1);
            out[n * EMB + c1] = 0.5f * (y0 + y1) + bb2_1 + resemb[rt * EMB + c1];
        }
    }
}

// ---------------- launch ----------------
extern "C" void kernel_launch(void* const* d_in, const int* in_sizes, int n_in,
                              void* d_out, int out_size) {
    const float* pn    = (const float*)d_in[0];
    const float* pca   = (const float*)d_in[1];
    const float* pc    = (const float*)d_in[2];
    const int*   rtype = (const int*)  d_in[3];
    /* batch d_in[4] unused */
    const int*   eidx  = (const int*)  d_in[5];
    const float* resemb= (const float*)d_in[6];
    const float* bbemb = (const float*)d_in[7];
    const float* ligW  = (const float*)d_in[8];
    const float* ligb  = (const float*)d_in[9];
    const float* bbW   = (const float*)d_in[10];
    const float* bbB   = (const float*)d_in[11];
    const float* e1W   = (const float*)d_in[12];
    const float* e1B   = (const float*)d_in[13];
    const float* e2aW  = (const float*)d_in[14];
    const float* e2aB  = (const float*)d_in[15];
    const float* e2bW  = (const float*)d_in[16];
    const float* e2bB  = (const float*)d_in[17];
    const float* sc1W  = (const float*)d_in[18];
    const float* sc1B  = (const float*)d_in[19];
    const float* sc2W  = (const float*)d_in[20];
    const float* sc2B  = (const float*)d_in[21];
    float* out = (float*)d_out;

    size_t smem_res = SMEM_RES_FLOATS * sizeof(float);
    cudaFuncSetAttribute(k_res, cudaFuncAttributeMaxDynamicSharedMemorySize, (int)smem_res);

    k_init<<<2048, 256>>>(pn, pca, pc, ligW, ligb, bbemb);
    k_edge<<<NEDGE / 256, 256>>>(eidx);
    k_lig<<<NODES / 32, 128>>>(bbemb);
    k_res<<<NRES / TRES, 128, smem_res>>>(pn, pca, pc, rtype, resemb,
                                          bbW, bbB, e1W, e1B,
                                          e2aW, e2aB, e2bW, e2bB,
                                          sc1W, sc1B, sc2W, sc2B, out);
}